// round 1
// baseline (speedup 1.0000x reference)
#include <cuda_runtime.h>
#include <cuda_bf16.h>

#define NN 50000
#define NE 800000
#define DIN 96
#define HID 128
#define NG 256
#define NCAT 256   // [W_rel | W_root] concatenated output width

// ---------------- scratch (__device__ globals; allocation-free) ----------------
__device__ __align__(16) int   g_deg[NN];
__device__ __align__(16) int   g_off[NN + 1];
__device__ __align__(16) int   g_cur[NN];
__device__ __align__(16) int   g_esrc[NE];
__device__ __align__(16) float g_ew[NE];
__device__ __align__(16) float g_Wc1[DIN * NCAT];   // [k][j] transposed+concat weights, layer1
__device__ __align__(16) float g_Wc2[HID * NCAT];   // layer2
__device__ __align__(16) float g_Y[NN * NCAT];      // GEMM output (reused both layers)
__device__ __align__(16) float g_h1[NN * HID];
__device__ __align__(16) float g_h2[NN * HID];

// ---------------- CSR build ----------------
__global__ void k_zero_deg() {
    int i = blockIdx.x * blockDim.x + threadIdx.x;
    if (i < NN) g_deg[i] = 0;
}

__global__ void k_count(const int* __restrict__ ei) {
    int e = blockIdx.x * blockDim.x + threadIdx.x;
    if (e < NE) atomicAdd(&g_deg[ei[NE + e]], 1);  // dst row
}

// single-block exclusive scan over 50000 degrees -> offsets (+ cursor copy)
__global__ void k_scan() {
    __shared__ int wsum[32];
    const int tid = threadIdx.x;
    const int CH = (NN + 1023) / 1024;  // 49
    const int base = tid * CH;
    int s = 0;
    for (int i = 0; i < CH; i++) {
        int idx = base + i;
        if (idx < NN) s += g_deg[idx];
    }
    int lane = tid & 31, w = tid >> 5;
    int v = s;
    #pragma unroll
    for (int o = 1; o < 32; o <<= 1) {
        int n = __shfl_up_sync(0xffffffffu, v, o);
        if (lane >= o) v += n;
    }
    if (lane == 31) wsum[w] = v;
    __syncthreads();
    if (w == 0) {
        int x = wsum[lane];
        #pragma unroll
        for (int o = 1; o < 32; o <<= 1) {
            int n = __shfl_up_sync(0xffffffffu, x, o);
            if (lane >= o) x += n;
        }
        wsum[lane] = x;
    }
    __syncthreads();
    int excl = v - s + (w > 0 ? wsum[w - 1] : 0);
    int run = excl;
    for (int i = 0; i < CH; i++) {
        int idx = base + i;
        if (idx < NN) {
            g_off[idx] = run;
            g_cur[idx] = run;
            run += g_deg[idx];
        }
    }
    if (tid == 1023) g_off[NN] = run;  // == NE
}

__global__ void k_scatter(const int* __restrict__ ei, const float* __restrict__ ea) {
    int e = blockIdx.x * blockDim.x + threadIdx.x;
    if (e < NE) {
        int d = ei[NE + e];
        int p = atomicAdd(&g_cur[d], 1);
        g_esrc[p] = ei[e];  // src row
        g_ew[p]   = ea[e];
    }
}

// ---------------- weight prep: transpose + concat into [K][256] ----------------
__global__ void k_prep_w(const float* __restrict__ Wr1, const float* __restrict__ Wro1,
                         const float* __restrict__ Wr3, const float* __restrict__ Wro3) {
    int idx = blockIdx.x * blockDim.x + threadIdx.x;
    const int n1 = DIN * NCAT;
    if (idx < n1) {
        int k = idx / NCAT, j = idx % NCAT;
        g_Wc1[idx] = (j < HID) ? Wr1[j * DIN + k] : Wro1[(j - HID) * DIN + k];
    } else if (idx < n1 + HID * NCAT) {
        int t = idx - n1;
        int k = t / NCAT, j = t % NCAT;
        g_Wc2[t] = (j < HID) ? Wr3[j * HID + k] : Wro3[(j - HID) * HID + k];
    }
}

// ---------------- fp32 SGEMM: g_Y[M][256] = A[M][K] @ Wc[K][256] ----------------
// K==96 -> A=param (x), B=g_Wc1 ; K==128 -> A=g_h1, B=g_Wc2
template <int K>
__global__ __launch_bounds__(256) void k_sgemm(const float* __restrict__ Ax) {
    const float* __restrict__ A = (K == 96) ? Ax : g_h1;
    const float* __restrict__ B = (K == 96) ? g_Wc1 : g_Wc2;
    __shared__ float As[8][128];
    __shared__ float Bs[8][128];
    const int tid = threadIdx.x;
    const int m0 = blockIdx.y * 128;
    const int n0 = blockIdx.x * 128;
    const int aRow = tid >> 1, aCol = (tid & 1) * 4;
    const int bRow = tid >> 5, bCol = (tid & 31) * 4;
    const int ty = tid >> 4, tx = tid & 15;
    float acc[8][8];
    #pragma unroll
    for (int i = 0; i < 8; i++)
        #pragma unroll
        for (int j = 0; j < 8; j++) acc[i][j] = 0.f;

    for (int k0 = 0; k0 < K; k0 += 8) {
        float4 av = make_float4(0.f, 0.f, 0.f, 0.f);
        int gr = m0 + aRow;
        if (gr < NN) av = *(const float4*)(A + gr * K + k0 + aCol);
        As[aCol + 0][aRow] = av.x;
        As[aCol + 1][aRow] = av.y;
        As[aCol + 2][aRow] = av.z;
        As[aCol + 3][aRow] = av.w;
        *(float4*)&Bs[bRow][bCol] = *(const float4*)(B + (k0 + bRow) * NCAT + n0 + bCol);
        __syncthreads();
        #pragma unroll
        for (int k = 0; k < 8; k++) {
            float ar[8], br[8];
            #pragma unroll
            for (int i = 0; i < 8; i++) ar[i] = As[k][ty * 8 + i];
            #pragma unroll
            for (int j = 0; j < 8; j++) br[j] = Bs[k][tx * 8 + j];
            #pragma unroll
            for (int i = 0; i < 8; i++)
                #pragma unroll
                for (int j = 0; j < 8; j++) acc[i][j] = fmaf(ar[i], br[j], acc[i][j]);
        }
        __syncthreads();
    }
    #pragma unroll
    for (int i = 0; i < 8; i++) {
        int gr = m0 + ty * 8 + i;
        if (gr < NN) {
            #pragma unroll
            for (int j = 0; j < 8; j += 4) {
                float4 v = make_float4(acc[i][j], acc[i][j + 1], acc[i][j + 2], acc[i][j + 3]);
                *(float4*)(g_Y + gr * NCAT + n0 + tx * 8 + j) = v;
            }
        }
    }
}

// ---------------- edge aggregation (warp per node, CSR gather, no atomics) ------
// layer==1: out g_h1, bias b_rel1, relu ; layer==2: out g_h2, bias b_rel3, no relu
__global__ void k_agg(const float* __restrict__ bias, int layer) {
    int node = (blockIdx.x * blockDim.x + threadIdx.x) >> 5;
    if (node >= NN) return;
    int lane = threadIdx.x & 31;
    int beg = g_off[node], end = g_off[node + 1];
    float ax = 0.f, ay = 0.f, az = 0.f, aw = 0.f;
    for (int e = beg; e < end; e++) {
        int s = g_esrc[e];
        float wt = g_ew[e];
        float4 v = *(const float4*)(g_Y + s * NCAT + 4 * lane);
        ax = fmaf(v.x, wt, ax);
        ay = fmaf(v.y, wt, ay);
        az = fmaf(v.z, wt, az);
        aw = fmaf(v.w, wt, aw);
    }
    float4 r = *(const float4*)(g_Y + node * NCAT + HID + 4 * lane);
    float4 b = *(const float4*)(bias + 4 * lane);
    ax += r.x + b.x;
    ay += r.y + b.y;
    az += r.z + b.z;
    aw += r.w + b.w;
    float* H;
    if (layer == 1) {
        ax = fmaxf(ax, 0.f); ay = fmaxf(ay, 0.f);
        az = fmaxf(az, 0.f); aw = fmaxf(aw, 0.f);
        H = g_h1;
    } else {
        H = g_h2;
    }
    *(float4*)(H + node * HID + 4 * lane) = make_float4(ax, ay, az, aw);
}

// ---------------- pooling + head (batch is sorted -> binary-search ranges) ------
__global__ void k_pool(const int* __restrict__ batch, const float* __restrict__ Wl,
                       const float* __restrict__ bl, float* __restrict__ out) {
    int g = blockIdx.x;
    int c = threadIdx.x;  // 128 threads
    // lower_bound(batch, g)
    int lo = 0, hi = NN;
    while (lo < hi) {
        int m = (lo + hi) >> 1;
        if (batch[m] < g) lo = m + 1; else hi = m;
    }
    // lower_bound(batch, g+1)
    int l = lo, h = NN;
    while (l < h) {
        int m = (l + h) >> 1;
        if (batch[m] < g + 1) l = m + 1; else h = m;
    }
    int cnt = l - lo;
    float s = 0.f;
    for (int i = lo; i < l; i++) s += g_h2[i * HID + c];
    float p = s / fmaxf((float)cnt, 1.f);
    float v = p * Wl[c];
    __shared__ float red[128];
    red[c] = v;
    __syncthreads();
    for (int st = 64; st > 0; st >>= 1) {
        if (c < st) red[c] += red[c + st];
        __syncthreads();
    }
    if (c == 0) out[g] = fmaxf(red[0] + bl[0], 0.f);
}

// ---------------- launch ----------------
extern "C" void kernel_launch(void* const* d_in, const int* in_sizes, int n_in,
                              void* d_out, int out_size) {
    const float* x     = (const float*)d_in[0];
    const int*   ei    = (const int*)d_in[1];
    const int*   batch = (const int*)d_in[2];
    const float* ea    = (const float*)d_in[3];
    const float* Wr1   = (const float*)d_in[4];
    const float* b1    = (const float*)d_in[5];
    const float* Wro1  = (const float*)d_in[6];
    const float* Wr3   = (const float*)d_in[7];
    const float* b3    = (const float*)d_in[8];
    const float* Wro3  = (const float*)d_in[9];
    const float* Wl    = (const float*)d_in[10];
    const float* bl    = (const float*)d_in[11];
    float* out = (float*)d_out;

    k_zero_deg<<<(NN + 255) / 256, 256>>>();
    k_count<<<(NE + 255) / 256, 256>>>(ei);
    k_scan<<<1, 1024>>>();
    k_scatter<<<(NE + 255) / 256, 256>>>(ei, ea);
    k_prep_w<<<((DIN + HID) * NCAT + 255) / 256, 256>>>(Wr1, Wro1, Wr3, Wro3);

    dim3 ggrid(2, (NN + 127) / 128);
    // layer 1
    k_sgemm<96><<<ggrid, 256>>>(x);
    k_agg<<<(NN * 32 + 255) / 256, 256>>>(b1, 1);
    // layer 2
    k_sgemm<128><<<ggrid, 256>>>(nullptr);
    k_agg<<<(NN * 32 + 255) / 256, 256>>>(b3, 2);
    // pool + head
    k_pool<<<NG, 128>>>(batch, Wl, bl, out);
}